// round 2
// baseline (speedup 1.0000x reference)
#include <cuda_runtime.h>

// Haar pair transform: x (64, 4096, 256) f32 -> out (64, 2048, 512) f32
// Chunk-local identity mapping: each contiguous 512-float chunk transforms in place:
//   out[2f]   = (in[f] + in[f+256]) * INV_SQRT2
//   out[2f+1] = (in[f] - in[f+256]) * INV_SQRT2
//
// R2: ILP x2 — each thread produces TWO output float4s of the same chunk,
// front-batching 4 independent LDG.64 (__ldcg, no L1 allocate) to double
// per-warp bytes-in-flight. All loads and stores remain perfectly coalesced.

__global__ void __launch_bounds__(256) haar_kernel(
    const float2* __restrict__ in2,   // input viewed as float2
    float4* __restrict__ out4,        // output viewed as float4
    int nt)                           // total threads = n4/2
{
    int t = blockIdx.x * blockDim.x + threadIdx.x;
    if (t >= nt) return;

    const float c = 0.70710678118654752440f;

    int chunk = t >> 6;        // 64 thread-items per chunk (each makes 2 float4s)
    int j     = t & 63;

    int ibase = (chunk << 8) + j;      // float2 index into chunk (256 float2 per chunk)

    // 4 independent loads, issued back-to-back (MLP=4)
    float2 a0 = __ldcg(&in2[ibase]);          // x0 pair, f = 2j
    float2 b0 = __ldcg(&in2[ibase + 128]);    // x1 pair
    float2 a1 = __ldcg(&in2[ibase + 64]);     // x0 pair, f = 2j + 128
    float2 b1 = __ldcg(&in2[ibase + 192]);    // x1 pair

    float4 o0;
    o0.x = (a0.x + b0.x) * c;
    o0.y = (a0.x - b0.x) * c;
    o0.z = (a0.y + b0.y) * c;
    o0.w = (a0.y - b0.y) * c;

    float4 o1;
    o1.x = (a1.x + b1.x) * c;
    o1.y = (a1.x - b1.x) * c;
    o1.z = (a1.y + b1.y) * c;
    o1.w = (a1.y - b1.y) * c;

    int obase = (chunk << 7) + j;      // 128 float4 outputs per chunk
    out4[obase]      = o0;
    out4[obase + 64] = o1;
}

extern "C" void kernel_launch(void* const* d_in, const int* in_sizes, int n_in,
                              void* d_out, int out_size)
{
    const float* x = (const float*)d_in[0];
    float* out = (float*)d_out;

    int nt = out_size / 8;                       // 8,388,608 threads (2 float4 each)
    int threads = 256;
    int blocks = (nt + threads - 1) / threads;   // 32,768 blocks

    haar_kernel<<<blocks, threads>>>(
        (const float2*)x, (float4*)out, nt);
}

// round 3
// speedup vs baseline: 1.0086x; 1.0086x over previous
#include <cuda_runtime.h>

// Haar pair transform: x (64, 4096, 256) f32 -> out (64, 2048, 512) f32
// Chunk-local identity mapping: each contiguous 512-float chunk transforms in place:
//   out[2f]   = (in[f] + in[f+256]) * INV_SQRT2
//   out[2f+1] = (in[f] - in[f+256]) * INV_SQRT2
//
// R3: 256-bit global accesses (sm_100+ LDG.E.256 / STG.E.256).
// Lane j of chunk loads x0[8j..8j+7] and x1[8j..8j+7] (two dense 256-bit loads,
// each warp instruction covers a contiguous 1KB span), produces the 16
// CONTIGUOUS output floats 16j..16j+15, stored as two dense 256-bit stores.
// The cA/cD interleave is resolved entirely in registers.

__global__ void __launch_bounds__(256) haar_kernel(
    const float* __restrict__ in,
    float* __restrict__ out,
    int nt)                           // total threads = out floats / 16
{
    int t = blockIdx.x * blockDim.x + threadIdx.x;
    if (t >= nt) return;

    const float c = 0.70710678118654752440f;

    int chunk = t >> 5;               // 32 lanes cover one 512-float chunk
    int j     = t & 31;

    const float* p0 = in + ((long)chunk << 9) + (j << 3);   // x0: 8 floats
    const float* p1 = p0 + 256;                             // x1: 8 floats

    float a0,a1,a2,a3,a4,a5,a6,a7;
    float b0,b1,b2,b3,b4,b5,b6,b7;

    asm volatile("ld.global.v8.f32 {%0,%1,%2,%3,%4,%5,%6,%7}, [%8];"
        : "=f"(a0),"=f"(a1),"=f"(a2),"=f"(a3),
          "=f"(a4),"=f"(a5),"=f"(a6),"=f"(a7)
        : "l"(p0));
    asm volatile("ld.global.v8.f32 {%0,%1,%2,%3,%4,%5,%6,%7}, [%8];"
        : "=f"(b0),"=f"(b1),"=f"(b2),"=f"(b3),
          "=f"(b4),"=f"(b5),"=f"(b6),"=f"(b7)
        : "l"(p1));

    float* q = out + ((long)chunk << 9) + (j << 4);         // 16 contiguous outputs

    // first 8 outputs: f = 8j .. 8j+3
    float o0 = (a0 + b0) * c, o1 = (a0 - b0) * c;
    float o2 = (a1 + b1) * c, o3 = (a1 - b1) * c;
    float o4 = (a2 + b2) * c, o5 = (a2 - b2) * c;
    float o6 = (a3 + b3) * c, o7 = (a3 - b3) * c;

    asm volatile("st.global.v8.f32 [%0], {%1,%2,%3,%4,%5,%6,%7,%8};"
        :: "l"(q),
           "f"(o0),"f"(o1),"f"(o2),"f"(o3),
           "f"(o4),"f"(o5),"f"(o6),"f"(o7)
        : "memory");

    // second 8 outputs: f = 8j+4 .. 8j+7
    float p0o = (a4 + b4) * c, p1o = (a4 - b4) * c;
    float p2o = (a5 + b5) * c, p3o = (a5 - b5) * c;
    float p4o = (a6 + b6) * c, p5o = (a6 - b6) * c;
    float p6o = (a7 + b7) * c, p7o = (a7 - b7) * c;

    asm volatile("st.global.v8.f32 [%0], {%1,%2,%3,%4,%5,%6,%7,%8};"
        :: "l"(q + 8),
           "f"(p0o),"f"(p1o),"f"(p2o),"f"(p3o),
           "f"(p4o),"f"(p5o),"f"(p6o),"f"(p7o)
        : "memory");
}

extern "C" void kernel_launch(void* const* d_in, const int* in_sizes, int n_in,
                              void* d_out, int out_size)
{
    const float* x = (const float*)d_in[0];
    float* out = (float*)d_out;

    int nt = out_size / 16;                      // 4,194,304 threads (16 floats out each)
    int threads = 256;
    int blocks = (nt + threads - 1) / threads;   // 16,384 blocks

    haar_kernel<<<blocks, threads>>>(x, out, nt);
}